// round 6
// baseline (speedup 1.0000x reference)
#include <cuda_runtime.h>
#include <cstdint>

// ---------------------------------------------------------------------------
// HierarchicalDownTopFusion — fully fused tf32 mma.sync implementation.
//
// Math (exact rewrite of reference):
//   g_m   = gelu(LN(pool4(small, adj[m]) @ W1 + b1))           m = 0..3
//   h2    = mean(medium) @ W1' + (Sum_m g_m) @ (0.25*W2@W1') + (b2@W1' + b1')
//   out   = global + gelu(LN(h2)) @ W2' + b2'
// C = 0.25*W2@W1' and bias2 = b2@W1'+b1' are precomputed per launch (cheap).
// All GEMM operands rounded to tf32 (cvt.rna), fp32 accumulation.
// ---------------------------------------------------------------------------

#define B_ROWS 65536
#define IN_DIM 768
#define HID    256
#define TM     64          // rows per CTA
#define AP     36          // abuf pitch (floats)  -> conflict-free A frags
#define WP     36          // wbuf pitch (floats)  -> conflict-free B frags
#define HP     258         // hbuf pitch
#define GP     260         // gsum pitch (A-operand friendly)

#define SMEM_FLOATS (TM*AP + 256*WP + TM*HP + TM*GP)   // 44672
#define SMEM_BYTES  (SMEM_FLOATS * 4)                  // 178688 B

// Weight scratch (module-static device memory — allowed)
__device__ __align__(16) float g_W1t [HID * IN_DIM];  // [n=256][k=768] = sm_w1^T (tf32)
__device__ __align__(16) float g_W1pt[HID * IN_DIM];  // [n=256][k=768] = mg_w1^T (tf32)
__device__ __align__(16) float g_W2pt[IN_DIM * HID];  // [n=768][k=256] = mg_w2^T (tf32)
__device__ __align__(16) float g_Cs  [HID * HID];     // [n=256][k=256] = (0.25*sm_w2@mg_w1)^T (tf32)
__device__ __align__(16) float g_bias2[HID];          // sm_b2@mg_w1 + mg_b1 (fp32)

__constant__ int c_adj[4][4] = {{0,1,3,4},{1,2,4,5},{3,4,6,7},{4,5,7,8}};

__device__ __forceinline__ float to_tf32(float x){
    uint32_t u; asm("cvt.rna.tf32.f32 %0, %1;" : "=r"(u) : "f"(x));
    return __uint_as_float(u);
}

__device__ __forceinline__ void mma8(float* d, const uint32_t* a, uint32_t b0, uint32_t b1){
    asm("mma.sync.aligned.m16n8k8.row.col.f32.tf32.tf32.f32 "
        "{%0,%1,%2,%3}, {%4,%5,%6,%7}, {%8,%9}, {%0,%1,%2,%3};\n"
        : "+f"(d[0]), "+f"(d[1]), "+f"(d[2]), "+f"(d[3])
        : "r"(a[0]), "r"(a[1]), "r"(a[2]), "r"(a[3]), "r"(b0), "r"(b1));
}

// ------------------------------- prep kernels ------------------------------

__global__ void prep_transpose(const float* __restrict__ smw1,
                               const float* __restrict__ mgw1,
                               const float* __restrict__ mgw2){
    int k = blockIdx.x;     // 0..767
    int n = threadIdx.x;    // 0..255
    g_W1t [n*IN_DIM + k] = to_tf32(smw1[k*HID + n]);
    g_W1pt[n*IN_DIM + k] = to_tf32(mgw1[k*HID + n]);
    // W2pt[n2=blockIdx][k2=thread] = mg_w2[k2*768 + n2]
    g_W2pt[k*HID + n]    = to_tf32(mgw2[n*IN_DIM + k]);
}

__global__ void prep_C(const float* __restrict__ smw2, const float* __restrict__ mgw1){
    int k = blockIdx.x;     // 0..255 (g-dim)
    int n = threadIdx.x;    // 0..255 (out-dim)
    float acc = 0.f;
    for (int t = 0; t < IN_DIM; t++)
        acc += smw2[k*IN_DIM + t] * mgw1[t*HID + n];
    g_Cs[n*HID + k] = to_tf32(0.25f * acc);
}

__global__ void prep_bias(const float* __restrict__ smb2, const float* __restrict__ mgw1,
                          const float* __restrict__ mgb1){
    int n = threadIdx.x;
    float acc = mgb1[n];
    for (int t = 0; t < IN_DIM; t++)
        acc += smb2[t] * mgw1[t*HID + n];
    g_bias2[n] = acc;
}

// ------------------------------- main kernel -------------------------------

// mma over one K-chunk of 32: A [64 x 32] (pitch APITCH), W [256 x 32] (pitch WP)
template<bool CVT, int APITCH>
__device__ __forceinline__ void mma_chunk(float d[2][8][4], const float* __restrict__ A,
                                          const float* __restrict__ W,
                                          int wm, int wn, int gid, int tig){
#pragma unroll
    for (int ks = 0; ks < 4; ks++){
        uint32_t a[2][4];
#pragma unroll
        for (int mt = 0; mt < 2; mt++){
            int r = wm*32 + mt*16 + gid;
            int c = ks*8 + tig;
            float a0 = A[r*APITCH + c];
            float a1 = A[(r+8)*APITCH + c];
            float a2 = A[r*APITCH + c + 4];
            float a3 = A[(r+8)*APITCH + c + 4];
            if (CVT){ a0 = to_tf32(a0); a1 = to_tf32(a1); a2 = to_tf32(a2); a3 = to_tf32(a3); }
            a[mt][0] = __float_as_uint(a0); a[mt][1] = __float_as_uint(a1);
            a[mt][2] = __float_as_uint(a2); a[mt][3] = __float_as_uint(a3);
        }
#pragma unroll
        for (int nt = 0; nt < 8; nt++){
            int n  = wn*64 + nt*8 + gid;
            int kk = ks*8 + tig;
            uint32_t b0 = __float_as_uint(W[n*WP + kk]);
            uint32_t b1 = __float_as_uint(W[n*WP + kk + 4]);
            mma8(d[0][nt], a[0], b0, b1);
            mma8(d[1][nt], a[1], b0, b1);
        }
    }
}

__device__ __forceinline__ void zero_d(float d[2][8][4]){
#pragma unroll
    for (int mt = 0; mt < 2; mt++)
#pragma unroll
    for (int nt = 0; nt < 8; nt++)
#pragma unroll
    for (int j = 0; j < 4; j++) d[mt][nt][j] = 0.f;
}

// stage one [256 x 32] weight chunk into wbuf (rows = n, pre-tf32 in gmem)
__device__ __forceinline__ void load_w_chunk(float* wbuf, const float* __restrict__ Wg,
                                             int rowstride_f4, int kc, int tid){
    const float4* W4 = (const float4*)Wg;
    float4* wb4 = (float4*)wbuf;
#pragma unroll
    for (int i = 0; i < 8; i++){
        int idx = i*256 + tid;
        int n = idx >> 3, kk = idx & 7;
        wb4[n*9 + kk] = W4[n*rowstride_f4 + kc*8 + kk];
    }
}

// pool 4 slabs of [64 rows x 32 cols] into abuf (mean * 0.25, tf32-rounded)
__device__ __forceinline__ void pool4_chunk(float* abuf, const float* __restrict__ base,
                                            int i0, int i1, int i2, int i3,
                                            int row0, int kc, int tid){
    const int SLAB = B_ROWS * (IN_DIM/4);
    const float4* S4 = (const float4*)base;
    float4* ab4 = (float4*)abuf;
#pragma unroll
    for (int i = 0; i < 2; i++){
        int idx = i*256 + tid;
        int r = idx >> 3, kk = idx & 7;
        int ro = (row0 + r)*(IN_DIM/4) + kc*8 + kk;
        float4 v0 = S4[i0*SLAB + ro];
        float4 v1 = S4[i1*SLAB + ro];
        float4 v2 = S4[i2*SLAB + ro];
        float4 v3 = S4[i3*SLAB + ro];
        float4 o;
        o.x = to_tf32(0.25f*(v0.x+v1.x+v2.x+v3.x));
        o.y = to_tf32(0.25f*(v0.y+v1.y+v2.y+v3.y));
        o.z = to_tf32(0.25f*(v0.z+v1.z+v2.z+v3.z));
        o.w = to_tf32(0.25f*(v0.w+v1.w+v2.w+v3.w));
        ab4[r*9 + kk] = o;
    }
}

__device__ __forceinline__ void store_h(const float d[2][8][4], float* hbuf,
                                        int wm, int wn, int gid, int tig){
#pragma unroll
    for (int mt = 0; mt < 2; mt++)
#pragma unroll
    for (int nt = 0; nt < 8; nt++){
        int r = wm*32 + mt*16 + gid;
        int c = wn*64 + nt*8 + tig*2;
        *(float2*)(hbuf + r*HP + c)     = make_float2(d[mt][nt][0], d[mt][nt][1]);
        *(float2*)(hbuf + (r+8)*HP + c) = make_float2(d[mt][nt][2], d[mt][nt][3]);
    }
}

// LayerNorm(256) + exact GELU; 4 threads per row, shfl reduce.
// ACC: gsum += gelu   (medium accumulation, fp32)
// !ACC: gsum = tf32(gelu)  (g2, pre-rounded for the final GEMM A operand)
template<bool ACC>
__device__ __forceinline__ void ln_gelu_ep(const float* hbuf, float* gsum,
                                           const float* __restrict__ bias,
                                           const float* __restrict__ gw,
                                           const float* __restrict__ bw, int tid){
    int r = tid >> 2, q = tid & 3;
    const float* hr = hbuf + r*HP;
    float s1 = 0.f, s2 = 0.f;
#pragma unroll 8
    for (int j = 0; j < 64; j++){
        int k = q*64 + j;
        float v = hr[k] + bias[k];
        s1 += v; s2 += v*v;
    }
    s1 += __shfl_xor_sync(0xffffffffu, s1, 1);
    s2 += __shfl_xor_sync(0xffffffffu, s2, 1);
    s1 += __shfl_xor_sync(0xffffffffu, s1, 2);
    s2 += __shfl_xor_sync(0xffffffffu, s2, 2);
    float mu   = s1 * (1.f/256.f);
    float var  = s2 * (1.f/256.f) - mu*mu;
    float rstd = rsqrtf(var + 1e-5f);
#pragma unroll 4
    for (int j = 0; j < 64; j++){
        int k = q*64 + j;
        float v  = (hr[k] + bias[k] - mu) * rstd * gw[k] + bw[k];
        float gl = 0.5f * v * (1.f + erff(v * 0.70710678118654752f));
        if (ACC) gsum[r*GP + k] += gl;
        else     gsum[r*GP + k]  = to_tf32(gl);
    }
}

__global__ __launch_bounds__(256, 1)
void fused_main(const float* __restrict__ gf, const float* __restrict__ med,
                const float* __restrict__ sml,
                const float* __restrict__ sm_b1, const float* __restrict__ sm_g,
                const float* __restrict__ sm_be,
                const float* __restrict__ mg_g,  const float* __restrict__ mg_be,
                const float* __restrict__ mg_b2,
                float* __restrict__ out){
    extern __shared__ float smem[];
    float* abuf = smem;                    // [64][36]
    float* wbuf = abuf + TM*AP;            // [256][36]
    float* hbuf = wbuf + 256*WP;           // [64][258]
    float* gsum = hbuf + TM*HP;            // [64][260]

    const int tid  = threadIdx.x;
    const int lane = tid & 31, wid = tid >> 5;
    const int gid  = lane >> 2, tig = lane & 3;
    const int wm   = wid & 1,  wn  = wid >> 1;     // 2(M) x 4(N) warps
    const int row0 = blockIdx.x * TM;

    for (int i = tid; i < TM*GP; i += 256) gsum[i] = 0.f;
    __syncthreads();

    float d[2][8][4];

    // ---- MLP1 for the 4 medium nodes: accumulate Sum_m gelu(LN(.)) into gsum
    for (int m = 0; m < 4; m++){
        zero_d(d);
        int i0 = c_adj[m][0], i1 = c_adj[m][1], i2 = c_adj[m][2], i3 = c_adj[m][3];
        for (int kc = 0; kc < IN_DIM/32; kc++){
            pool4_chunk(abuf, sml, i0, i1, i2, i3, row0, kc, tid);
            load_w_chunk(wbuf, g_W1t, IN_DIM/4, kc, tid);
            __syncthreads();
            mma_chunk<false, AP>(d, abuf, wbuf, wm, wn, gid, tig);
            __syncthreads();
        }
        store_h(d, hbuf, wm, wn, gid, tig);
        __syncthreads();
        ln_gelu_ep<true>(hbuf, gsum, sm_b1, sm_g, sm_be, tid);
        __syncthreads();
    }

    // ---- h2 = mean(medium)@W1' + gsum@Cs + bias2
    zero_d(d);
    for (int kc = 0; kc < IN_DIM/32; kc++){
        pool4_chunk(abuf, med, 0, 1, 2, 3, row0, kc, tid);
        load_w_chunk(wbuf, g_W1pt, IN_DIM/4, kc, tid);
        __syncthreads();
        mma_chunk<false, AP>(d, abuf, wbuf, wm, wn, gid, tig);
        __syncthreads();
    }
    for (int kc = 0; kc < HID/32; kc++){
        load_w_chunk(wbuf, g_Cs, HID/4, kc, tid);
        __syncthreads();
        mma_chunk<true, GP>(d, gsum + kc*32, wbuf, wm, wn, gid, tig);
        __syncthreads();
    }
    store_h(d, hbuf, wm, wn, gid, tig);
    __syncthreads();
    ln_gelu_ep<false>(hbuf, gsum, g_bias2, mg_g, mg_be, tid);   // g2 -> gsum (tf32)
    __syncthreads();

    // ---- out = g2 @ W2' + global + mg_b2   (N=768 in three 256-wide passes)
    for (int np = 0; np < 3; np++){
        zero_d(d);
        for (int kc = 0; kc < HID/32; kc++){
            load_w_chunk(wbuf, g_W2pt + np*256*HID, HID/4, kc, tid);
            __syncthreads();
            mma_chunk<false, GP>(d, gsum + kc*32, wbuf, wm, wn, gid, tig);
            __syncthreads();
        }
#pragma unroll
        for (int mt = 0; mt < 2; mt++)
#pragma unroll
        for (int nt = 0; nt < 8; nt++){
            int r  = wm*32 + mt*16 + gid;
            int c  = np*256 + wn*64 + nt*8 + tig*2;
            int ro = (row0 + r) * IN_DIM + c;
            float2 bv  = *(const float2*)(mg_b2 + c);
            float2 gv  = *(const float2*)(gf + ro);
            *(float2*)(out + ro) = make_float2(d[mt][nt][0] + gv.x + bv.x,
                                               d[mt][nt][1] + gv.y + bv.y);
            int ro8 = ro + 8*IN_DIM;
            float2 gv2 = *(const float2*)(gf + ro8);
            *(float2*)(out + ro8) = make_float2(d[mt][nt][2] + gv2.x + bv.x,
                                                d[mt][nt][3] + gv2.y + bv.y);
        }
    }
}

// ------------------------------- launcher ----------------------------------

extern "C" void kernel_launch(void* const* d_in, const int* in_sizes, int n_in,
                              void* d_out, int out_size){
    const float* gf   = (const float*)d_in[0];
    const float* med  = (const float*)d_in[1];
    const float* sml  = (const float*)d_in[2];
    const float* smw1 = (const float*)d_in[3];
    const float* smb1 = (const float*)d_in[4];
    const float* smg  = (const float*)d_in[5];
    const float* smbe = (const float*)d_in[6];
    const float* smw2 = (const float*)d_in[7];
    const float* smb2 = (const float*)d_in[8];
    const float* mgw1 = (const float*)d_in[9];
    const float* mgb1 = (const float*)d_in[10];
    const float* mgg  = (const float*)d_in[11];
    const float* mgbe = (const float*)d_in[12];
    const float* mgw2 = (const float*)d_in[13];
    const float* mgb2 = (const float*)d_in[14];
    float* out = (float*)d_out;
    (void)in_sizes; (void)n_in; (void)out_size;

    cudaFuncSetAttribute(fused_main, cudaFuncAttributeMaxDynamicSharedMemorySize, SMEM_BYTES);

    prep_transpose<<<IN_DIM, HID>>>(smw1, mgw1, mgw2);
    prep_C<<<HID, HID>>>(smw2, mgw1);
    prep_bias<<<1, HID>>>(smb2, mgw1, mgb1);
    fused_main<<<B_ROWS/TM, 256, SMEM_BYTES>>>(gf, med, sml, smb1, smg, smbe,
                                               mgg, mgbe, mgb2, out);
}

// round 7
// speedup vs baseline: 1.4806x; 1.4806x over previous
#include <cuda_runtime.h>
#include <cstdint>

// ---------------------------------------------------------------------------
// HierarchicalDownTopFusion — fused tf32 mma.sync, pipelined (R6).
//
//   g_m   = gelu(LN(pool4(small, adj[m]) @ W1 + b1))           m = 0..3
//   h2    = mean(medium) @ W1' + (Sum_m g_m) @ (0.25*W2@W1') + (b2@W1' + b1')
//   out   = global + gelu(LN(h2)) @ W2' + b2'
//
// R6: cp.async double-buffered weights, register-prefetched pooled A,
//     in-register LayerNorm epilogue (no hbuf), 1 barrier per K-chunk.
// ---------------------------------------------------------------------------

#define B_ROWS 65536
#define IN_DIM 768
#define HID    256
#define TM     64
#define AP     36          // abuf pitch
#define WP     36          // wbuf pitch
#define GP     260         // gsum pitch
#define NC1    (IN_DIM/32) // 24
#define NC2    (HID/32)    // 8

// smem: gsum[64][260] + 2*abuf[64][36] + 2*wbuf[256][36] + params 6*256 + scratch 512
#define SMEM_FLOATS (TM*GP + 2*TM*AP + 2*256*WP + 6*256 + 512)
#define SMEM_BYTES  (SMEM_FLOATS * 4)   // 166912

__device__ __align__(16) float g_W1t [HID * IN_DIM];  // sm_w1^T  (tf32)
__device__ __align__(16) float g_W1pt[HID * IN_DIM];  // mg_w1^T  (tf32)
__device__ __align__(16) float g_W2pt[IN_DIM * HID];  // mg_w2^T  (tf32)
__device__ __align__(16) float g_Cs  [HID * HID];     // (0.25*sm_w2@mg_w1)^T (tf32)
__device__ __align__(16) float g_bias2[HID];          // sm_b2@mg_w1 + mg_b1

__constant__ int c_adj[4][4] = {{0,1,3,4},{1,2,4,5},{3,4,6,7},{4,5,7,8}};

__device__ __forceinline__ float to_tf32(float x){
    uint32_t u; asm("cvt.rna.tf32.f32 %0, %1;" : "=r"(u) : "f"(x));
    return __uint_as_float(u);
}

__device__ __forceinline__ void mma8(float* d, const uint32_t* a, uint32_t b0, uint32_t b1){
    asm("mma.sync.aligned.m16n8k8.row.col.f32.tf32.tf32.f32 "
        "{%0,%1,%2,%3}, {%4,%5,%6,%7}, {%8,%9}, {%0,%1,%2,%3};\n"
        : "+f"(d[0]), "+f"(d[1]), "+f"(d[2]), "+f"(d[3])
        : "r"(a[0]), "r"(a[1]), "r"(a[2]), "r"(a[3]), "r"(b0), "r"(b1));
}

__device__ __forceinline__ uint32_t smem_u32(const void* p){
    return (uint32_t)__cvta_generic_to_shared(p);
}
__device__ __forceinline__ void cpa16(uint32_t dst, const void* src){
    asm volatile("cp.async.ca.shared.global [%0], [%1], 16;\n" :: "r"(dst), "l"(src));
}
#define CP_COMMIT asm volatile("cp.async.commit_group;\n")
#define CP_WAIT0  asm volatile("cp.async.wait_group 0;\n")

// ------------------------------- prep kernels ------------------------------

__global__ void prep_transpose(const float* __restrict__ smw1,
                               const float* __restrict__ mgw1,
                               const float* __restrict__ mgw2){
    int k = blockIdx.x;     // 0..767
    int n = threadIdx.x;    // 0..255
    g_W1t [n*IN_DIM + k] = to_tf32(smw1[k*HID + n]);
    g_W1pt[n*IN_DIM + k] = to_tf32(mgw1[k*HID + n]);
    g_W2pt[k*HID + n]    = to_tf32(mgw2[n*IN_DIM + k]);
}

__global__ void prep_C(const float* __restrict__ smw2, const float* __restrict__ mgw1){
    int k = blockIdx.x;     // 0..255
    int n = threadIdx.x;    // 0..255
    float acc = 0.f;
    for (int t = 0; t < IN_DIM; t++)
        acc += smw2[k*IN_DIM + t] * mgw1[t*HID + n];
    g_Cs[n*HID + k] = to_tf32(0.25f * acc);
}

__global__ void prep_bias(const float* __restrict__ smb2, const float* __restrict__ mgw1,
                          const float* __restrict__ mgb1){
    int n = threadIdx.x;
    float acc = mgb1[n];
    for (int t = 0; t < IN_DIM; t++)
        acc += smb2[t] * mgw1[t*HID + n];
    g_bias2[n] = acc;
}

// ------------------------------- device helpers ----------------------------

template<bool CVT, int APITCH>
__device__ __forceinline__ void mma_chunk(float d[2][8][4], const float* __restrict__ A,
                                          const float* __restrict__ W,
                                          int wm, int wn, int gid, int tig){
#pragma unroll
    for (int ks = 0; ks < 4; ks++){
        uint32_t a[2][4];
#pragma unroll
        for (int mt = 0; mt < 2; mt++){
            int r = wm*32 + mt*16 + gid;
            int c = ks*8 + tig;
            float a0 = A[r*APITCH + c];
            float a1 = A[(r+8)*APITCH + c];
            float a2 = A[r*APITCH + c + 4];
            float a3 = A[(r+8)*APITCH + c + 4];
            if (CVT){ a0 = to_tf32(a0); a1 = to_tf32(a1); a2 = to_tf32(a2); a3 = to_tf32(a3); }
            a[mt][0] = __float_as_uint(a0); a[mt][1] = __float_as_uint(a1);
            a[mt][2] = __float_as_uint(a2); a[mt][3] = __float_as_uint(a3);
        }
#pragma unroll
        for (int nt = 0; nt < 8; nt++){
            int n  = wn*64 + nt*8 + gid;
            int kk = ks*8 + tig;
            uint32_t b0 = __float_as_uint(W[n*WP + kk]);
            uint32_t b1 = __float_as_uint(W[n*WP + kk + 4]);
            mma8(d[0][nt], a[0], b0, b1);
            mma8(d[1][nt], a[1], b0, b1);
        }
    }
}

__device__ __forceinline__ void zero_d(float d[2][8][4]){
#pragma unroll
    for (int mt = 0; mt < 2; mt++)
#pragma unroll
    for (int nt = 0; nt < 8; nt++)
#pragma unroll
    for (int j = 0; j < 4; j++) d[mt][nt][j] = 0.f;
}

// stage one [256 x 32] weight chunk into wbuf via cp.async (weights pre-tf32)
__device__ __forceinline__ void stage_w(float* wbuf, const float* __restrict__ Wg,
                                        int rowstride, int kc, int tid){
    uint32_t wb = smem_u32(wbuf);
#pragma unroll
    for (int i = 0; i < 8; i++){
        int idx = i*256 + tid;
        int n = idx >> 3, g = idx & 7;
        cpa16(wb + (uint32_t)(n*WP + g*4)*4u, Wg + n*rowstride + kc*32 + g*4);
    }
}

// raw loads for one pooled [64 x 32] A chunk (4 slabs)
struct PoolLd { float4 v[2][4]; };

__device__ __forceinline__ void pool_ld(PoolLd& P, const float4* __restrict__ S4,
                                        int i0,int i1,int i2,int i3,
                                        int row0, int kc, int tid){
    const int SLAB = B_ROWS * (IN_DIM/4);
#pragma unroll
    for (int i = 0; i < 2; i++){
        int idx = i*256 + tid;
        int r = idx >> 3, kk = idx & 7;
        int ro = (row0 + r)*(IN_DIM/4) + kc*8 + kk;
        P.v[i][0] = __ldg(S4 + i0*SLAB + ro);
        P.v[i][1] = __ldg(S4 + i1*SLAB + ro);
        P.v[i][2] = __ldg(S4 + i2*SLAB + ro);
        P.v[i][3] = __ldg(S4 + i3*SLAB + ro);
    }
}

__device__ __forceinline__ void pool_st(const PoolLd& P, float* abuf, int tid){
    float4* ab4 = (float4*)abuf;
#pragma unroll
    for (int i = 0; i < 2; i++){
        int idx = i*256 + tid;
        int r = idx >> 3, kk = idx & 7;
        float4 o;
        o.x = to_tf32(0.25f*(P.v[i][0].x + P.v[i][1].x + P.v[i][2].x + P.v[i][3].x));
        o.y = to_tf32(0.25f*(P.v[i][0].y + P.v[i][1].y + P.v[i][2].y + P.v[i][3].y));
        o.z = to_tf32(0.25f*(P.v[i][0].z + P.v[i][1].z + P.v[i][2].z + P.v[i][3].z));
        o.w = to_tf32(0.25f*(P.v[i][0].w + P.v[i][1].w + P.v[i][2].w + P.v[i][3].w));
        ab4[r*9 + kk] = o;
    }
}

// GEMM over K=768 with pooled A, double-buffered A (reg prefetch) + W (cp.async)
__device__ __forceinline__ void gemm_pooled(float d[2][8][4],
    const float4* __restrict__ S4, int i0,int i1,int i2,int i3, int row0,
    const float* __restrict__ Wg,
    float* ab0, float* ab1, float* wb0, float* wb1,
    int wm,int wn,int gid,int tig,int tid)
{
    PoolLd P;
    stage_w(wb0, Wg, IN_DIM, 0, tid);
    CP_COMMIT;
    pool_ld(P, S4, i0,i1,i2,i3, row0, 0, tid);
    pool_st(P, ab0, tid);
    CP_WAIT0;
    __syncthreads();
#pragma unroll 1
    for (int kc = 0; kc < NC1; kc++){
        float* ac = (kc & 1) ? ab1 : ab0;
        float* wc = (kc & 1) ? wb1 : wb0;
        if (kc + 1 < NC1){
            float* wnx = (kc & 1) ? wb0 : wb1;
            stage_w(wnx, Wg, IN_DIM, kc+1, tid);
            CP_COMMIT;
            pool_ld(P, S4, i0,i1,i2,i3, row0, kc+1, tid);
            mma_chunk<false, AP>(d, ac, wc, wm, wn, gid, tig);
            float* anx = (kc & 1) ? ab0 : ab1;
            pool_st(P, anx, tid);
            CP_WAIT0;
        } else {
            mma_chunk<false, AP>(d, ac, wc, wm, wn, gid, tig);
        }
        __syncthreads();
    }
}

// GEMM with A already resident in smem (gsum), weights double-buffered
template<bool CVT>
__device__ __forceinline__ void gemm_smemA(float d[2][8][4], const float* Asm,
    const float* __restrict__ Wg, int rowstride, int nchunks,
    float* wb0, float* wb1, int wm,int wn,int gid,int tig,int tid)
{
    stage_w(wb0, Wg, rowstride, 0, tid);
    CP_COMMIT;
    CP_WAIT0;
    __syncthreads();
#pragma unroll 1
    for (int kc = 0; kc < nchunks; kc++){
        float* wc = (kc & 1) ? wb1 : wb0;
        if (kc + 1 < nchunks){
            float* wnx = (kc & 1) ? wb0 : wb1;
            stage_w(wnx, Wg, rowstride, kc+1, tid);
            CP_COMMIT;
        }
        mma_chunk<CVT, GP>(d, Asm + kc*32, wc, wm, wn, gid, tig);
        if (kc + 1 < nchunks) CP_WAIT0;
        __syncthreads();
    }
}

// In-register LayerNorm + exact GELU epilogue.
// ACC:  gsum += gelu(LN(d+b))      (fp32 accumulate across mediums)
// !ACC: gsum  = tf32(gelu(LN(d+b))) (g2, pre-rounded A for final GEMM)
template<bool ACC>
__device__ __forceinline__ void ln_gelu_reg(const float d[2][8][4], float* gsum,
        float* scratch,
        const float* bP, const float* gP, const float* beP,
        int wm,int wn,int gid,int tig)
{
    float bc[8][2];
#pragma unroll
    for (int nt = 0; nt < 8; nt++){
        int c = wn*64 + nt*8 + tig*2;
        bc[nt][0] = bP[c]; bc[nt][1] = bP[c+1];
    }
    float s1[2][2] = {{0,0},{0,0}}, s2[2][2] = {{0,0},{0,0}};
#pragma unroll
    for (int mt = 0; mt < 2; mt++)
#pragma unroll
    for (int nt = 0; nt < 8; nt++){
        float v0 = d[mt][nt][0] + bc[nt][0], v1 = d[mt][nt][1] + bc[nt][1];
        float v2 = d[mt][nt][2] + bc[nt][0], v3 = d[mt][nt][3] + bc[nt][1];
        s1[mt][0] += v0 + v1;  s2[mt][0] += v0*v0 + v1*v1;
        s1[mt][1] += v2 + v3;  s2[mt][1] += v2*v2 + v3*v3;
    }
#pragma unroll
    for (int mt = 0; mt < 2; mt++)
#pragma unroll
    for (int h = 0; h < 2; h++){
        s1[mt][h] += __shfl_xor_sync(0xffffffffu, s1[mt][h], 1);
        s2[mt][h] += __shfl_xor_sync(0xffffffffu, s2[mt][h], 1);
        s1[mt][h] += __shfl_xor_sync(0xffffffffu, s1[mt][h], 2);
        s2[mt][h] += __shfl_xor_sync(0xffffffffu, s2[mt][h], 2);
    }
    if (tig == 0){
#pragma unroll
        for (int mt = 0; mt < 2; mt++)
#pragma unroll
        for (int h = 0; h < 2; h++){
            int row = wm*32 + mt*16 + h*8 + gid;
            scratch[(row*4 + wn)*2 + 0] = s1[mt][h];
            scratch[(row*4 + wn)*2 + 1] = s2[mt][h];
        }
    }
    __syncthreads();
    float mu[2][2], rs[2][2];
#pragma unroll
    for (int mt = 0; mt < 2; mt++)
#pragma unroll
    for (int h = 0; h < 2; h++){
        int row = wm*32 + mt*16 + h*8 + gid;
        float S1 = 0.f, S2 = 0.f;
#pragma unroll
        for (int w = 0; w < 4; w++){
            S1 += scratch[(row*4 + w)*2 + 0];
            S2 += scratch[(row*4 + w)*2 + 1];
        }
        float m_  = S1 * (1.f/256.f);
        float var = S2 * (1.f/256.f) - m_*m_;
        mu[mt][h] = m_;
        rs[mt][h] = rsqrtf(var + 1e-5f);
    }
    float gc[8][2], bec[8][2];
#pragma unroll
    for (int nt = 0; nt < 8; nt++){
        int c = wn*64 + nt*8 + tig*2;
        gc[nt][0]  = gP[c];  gc[nt][1]  = gP[c+1];
        bec[nt][0] = beP[c]; bec[nt][1] = beP[c+1];
    }
#pragma unroll
    for (int mt = 0; mt < 2; mt++)
#pragma unroll
    for (int nt = 0; nt < 8; nt++){
        int rA = wm*32 + mt*16 + gid, rB = rA + 8;
        int c  = wn*64 + nt*8 + tig*2;
        float vs[4];
        vs[0] = (d[mt][nt][0] + bc[nt][0] - mu[mt][0])*rs[mt][0]*gc[nt][0] + bec[nt][0];
        vs[1] = (d[mt][nt][1] + bc[nt][1] - mu[mt][0])*rs[mt][0]*gc[nt][1] + bec[nt][1];
        vs[2] = (d[mt][nt][2] + bc[nt][0] - mu[mt][1])*rs[mt][1]*gc[nt][0] + bec[nt][0];
        vs[3] = (d[mt][nt][3] + bc[nt][1] - mu[mt][1])*rs[mt][1]*gc[nt][1] + bec[nt][1];
#pragma unroll
        for (int j = 0; j < 4; j++)
            vs[j] = 0.5f * vs[j] * (1.f + erff(vs[j] * 0.70710678118654752440f));
        if (ACC){
            gsum[rA*GP + c]     += vs[0];
            gsum[rA*GP + c + 1] += vs[1];
            gsum[rB*GP + c]     += vs[2];
            gsum[rB*GP + c + 1] += vs[3];
        } else {
            gsum[rA*GP + c]     = to_tf32(vs[0]);
            gsum[rA*GP + c + 1] = to_tf32(vs[1]);
            gsum[rB*GP + c]     = to_tf32(vs[2]);
            gsum[rB*GP + c + 1] = to_tf32(vs[3]);
        }
    }
    __syncthreads();
}

// ------------------------------- main kernel -------------------------------

__global__ __launch_bounds__(256, 1)
void fused_main(const float* __restrict__ gf, const float* __restrict__ med,
                const float* __restrict__ sml,
                const float* __restrict__ sm_b1, const float* __restrict__ sm_g,
                const float* __restrict__ sm_be,
                const float* __restrict__ mg_g,  const float* __restrict__ mg_be,
                const float* __restrict__ mg_b2,
                float* __restrict__ out){
    extern __shared__ float smem[];
    float* gsum    = smem;                 // [64][260]
    float* ab0     = gsum + TM*GP;         // [64][36]
    float* ab1     = ab0  + TM*AP;
    float* wb0     = ab1  + TM*AP;         // [256][36]
    float* wb1     = wb0  + 256*WP;
    float* prm     = wb1  + 256*WP;        // 6 x 256
    float* scratch = prm  + 6*256;         // 512

    const int tid  = threadIdx.x;
    const int lane = tid & 31, wid = tid >> 5;
    const int gid  = lane >> 2, tig = lane & 3;
    const int wm   = wid & 1,  wn  = wid >> 1;
    const int row0 = blockIdx.x * TM;

    // stage per-column params + zero gsum
    prm[tid]        = sm_b1[tid];
    prm[256 + tid]  = sm_g[tid];
    prm[512 + tid]  = sm_be[tid];
    prm[768 + tid]  = g_bias2[tid];
    prm[1024 + tid] = mg_g[tid];
    prm[1280 + tid] = mg_be[tid];
    for (int i = tid; i < TM*GP; i += 256) gsum[i] = 0.f;
    __syncthreads();

    const float4* S4s = (const float4*)sml;
    const float4* S4m = (const float4*)med;
    float d[2][8][4];

    // ---- MLP1 x4: gsum += gelu(LN(pool4(small)@W1 + b1))
    for (int m = 0; m < 4; m++){
        zero_d(d);
        gemm_pooled(d, S4s, c_adj[m][0], c_adj[m][1], c_adj[m][2], c_adj[m][3],
                    row0, g_W1t, ab0, ab1, wb0, wb1, wm, wn, gid, tig, tid);
        ln_gelu_reg<true>(d, gsum, scratch, prm, prm+256, prm+512, wm, wn, gid, tig);
    }

    // ---- h2 = mean(medium)@W1' + gsum@Cs (+bias2 in LN); g2 -> gsum
    zero_d(d);
    gemm_pooled(d, S4m, 0, 1, 2, 3, row0, g_W1pt,
                ab0, ab1, wb0, wb1, wm, wn, gid, tig, tid);
    gemm_smemA<true>(d, gsum, g_Cs, HID, NC2, wb0, wb1, wm, wn, gid, tig, tid);
    ln_gelu_reg<false>(d, gsum, scratch, prm+768, prm+1024, prm+1280, wm, wn, gid, tig);

    // ---- out = g2 @ W2' + global + mg_b2   (three 256-wide N passes)
    for (int np = 0; np < 3; np++){
        zero_d(d);
        gemm_smemA<false>(d, gsum, g_W2pt + np*256*HID, HID, NC2,
                          wb0, wb1, wm, wn, gid, tig, tid);
#pragma unroll
        for (int mt = 0; mt < 2; mt++)
#pragma unroll
        for (int nt = 0; nt < 8; nt++){
            int r  = wm*32 + mt*16 + gid;
            int c  = np*256 + wn*64 + nt*8 + tig*2;
            int ro = (row0 + r) * IN_DIM + c;
            float2 bv = *(const float2*)(mg_b2 + c);
            float2 gv = __ldcs((const float2*)(gf + ro));
            __stcs((float2*)(out + ro),
                   make_float2(d[mt][nt][0] + gv.x + bv.x,
                               d[mt][nt][1] + gv.y + bv.y));
            int ro8 = ro + 8*IN_DIM;
            float2 gv2 = __ldcs((const float2*)(gf + ro8));
            __stcs((float2*)(out + ro8),
                   make_float2(d[mt][nt][2] + gv2.x + bv.x,
                               d[mt][nt][3] + gv2.y + bv.y));
        }
    }
}

// ------------------------------- launcher ----------------------------------

extern "C" void kernel_launch(void* const* d_in, const int* in_sizes, int n_in,
                              void* d_out, int out_size){
    const float* gf   = (const float*)d_in[0];
    const float* med  = (const float*)d_in[1];
    const float* sml  = (const float*)d_in[2];
    const float* smw1 = (const float*)d_in[3];
    const float* smb1 = (const float*)d_in[4];
    const float* smg  = (const float*)d_in[5];
    const float* smbe = (const float*)d_in[6];
    const float* smw2 = (const float*)d_in[7];
    const float* smb2 = (const float*)d_in[8];
    const float* mgw1 = (const float*)d_in[9];
    const float* mgb1 = (const float*)d_in[10];
    const float* mgg  = (const float*)d_in[11];
    const float* mgbe = (const float*)d_in[12];
    const float* mgw2 = (const float*)d_in[13];
    const float* mgb2 = (const float*)d_in[14];
    float* out = (float*)d_out;
    (void)in_sizes; (void)n_in; (void)out_size;

    cudaFuncSetAttribute(fused_main, cudaFuncAttributeMaxDynamicSharedMemorySize, SMEM_BYTES);

    prep_transpose<<<IN_DIM, HID>>>(smw1, mgw1, mgw2);
    prep_C<<<HID, HID>>>(smw2, mgw1);
    prep_bias<<<1, HID>>>(smb2, mgw1, mgb1);
    fused_main<<<B_ROWS/TM, 256, SMEM_BYTES>>>(gf, med, sml, smb1, smg, smbe,
                                               mgg, mgbe, mgb2, out);
}